// round 9
// baseline (speedup 1.0000x reference)
#include <cuda_runtime.h>

// ---------------- problem constants ----------------
#define NFD    101            // feature dim
#define UNITS  125            // GRU units
#define NG     375            // 3*UNITS
#define NGP    384            // gate-padded weight cols: z@0, r@128, h@256
#define OUT2   202            // 2*NFD
#define OUTP   256            // padded dense cols
#define OUTS   258            // ys smem row stride
#define XSTR   66             // xdup/hdup smem row stride (32 dup pairs + pad)
#define KS_    (UNITS*OUT2)   // 25250
#define NW     (KS_+OUT2)     // 25452
#define GAMMA_ 28
#define LAGT   56             // 70 - 14
#define BATCH  4096
#define TSEQ   70
#define CCONST 0.5413248546129181f   // log(expm1(1))

typedef unsigned long long ull;

// ---------------- scratch (device globals: no allocation allowed) ----------------
__device__ __align__(16) float g_Wk[NFD * NGP];            // (101,384) gate-padded
__device__ __align__(16) float g_U [UNITS * NGP];          // (125,384) gate-padded
__device__ __align__(16) float g_bzr[256];                 // z: b0z+b1z @0, r: b0r+b1r @128
__device__ __align__(16) float g_bxh[128];                 // b0 h-gate
__device__ __align__(16) float g_brh[128];                 // b1 h-gate
__device__ __align__(16) float g_wker [GAMMA_ * UNITS * OUTP]; // 28 x (125,256)
__device__ __align__(16) float g_wbias[GAMMA_ * OUTP];

// ---------------- math helpers ----------------
__device__ __forceinline__ float softplusf_(float x) {
    return (x > 20.f) ? x : log1pf(__expf(x));
}
__device__ __forceinline__ float sigmoidf_(float x) {
    return __fdividef(1.f, 1.f + __expf(-x));
}
__device__ __forceinline__ float tanhf_(float x) {
    float e = __expf(2.f * x);
    return 1.f - __fdividef(2.f, e + 1.f);
}
__device__ __forceinline__ ull ffma2(ull a, ull b, ull c) {
    ull d;
    asm("fma.rn.f32x2 %0, %1, %2, %3;" : "=l"(d) : "l"(a), "l"(b), "l"(c));
    return d;
}
__device__ __forceinline__ float2 unpk(ull v) {
    float2 f;
    asm("mov.b64 {%0, %1}, %2;" : "=f"(f.x), "=f"(f.y) : "l"(v));
    return f;
}

// ---------------- one fused GRU step, gates fully register-resident ----------------
// xd: duplicated activations [NFD][XSTR]; hd: duplicated hidden [128][XSTR]
// thread (tx<64, ty<4): rows m = ty*8+i, unit pair (2tx, 2tx+1) in every gate.
__device__ __forceinline__ void gru_step(const float* __restrict__ xd,
                                         float* __restrict__ hd,
                                         int tx, int ty)
{
    ull az[8], ar[8], axh[8], arh[8];
    {
        ull bz  = *reinterpret_cast<const ull*>(g_bzr + 2 * tx);
        ull br  = *reinterpret_cast<const ull*>(g_bzr + 128 + 2 * tx);
        ull bxh = *reinterpret_cast<const ull*>(g_bxh + 2 * tx);
        ull brh = *reinterpret_cast<const ull*>(g_brh + 2 * tx);
        #pragma unroll
        for (int i = 0; i < 8; i++) { az[i] = bz; ar[i] = br; axh[i] = bxh; arh[i] = brh; }
    }
    // pass A: x @ Wk  (z,r into shared accs; h-gate into axh)
    {
        const ull* W = reinterpret_cast<const ull*>(g_Wk) + tx;  // row stride 192 ull
        #pragma unroll 4
        for (int k = 0; k < NFD; k++) {
            ull wz = W[k * 192], wr = W[k * 192 + 64], wh = W[k * 192 + 128];
            #pragma unroll
            for (int i = 0; i < 8; i++) {
                ull xx = *reinterpret_cast<const ull*>(xd + k * XSTR + 2 * (ty * 8 + i));
                az[i]  = ffma2(xx, wz, az[i]);
                ar[i]  = ffma2(xx, wr, ar[i]);
                axh[i] = ffma2(xx, wh, axh[i]);
            }
        }
    }
    // pass B: h @ U  (z,r continue shared accs; h-gate into arh)
    {
        const ull* W = reinterpret_cast<const ull*>(g_U) + tx;
        #pragma unroll 4
        for (int k = 0; k < UNITS; k++) {
            ull wz = W[k * 192], wr = W[k * 192 + 64], wh = W[k * 192 + 128];
            #pragma unroll
            for (int i = 0; i < 8; i++) {
                ull xx = *reinterpret_cast<const ull*>(hd + k * XSTR + 2 * (ty * 8 + i));
                az[i]  = ffma2(xx, wz, az[i]);
                ar[i]  = ffma2(xx, wr, ar[i]);
                arh[i] = ffma2(xx, wh, arh[i]);
            }
        }
    }
    // read old h for the two owned units (before any gate write)
    float h0l[8], h0h[8];
    #pragma unroll
    for (int i = 0; i < 8; i++) {
        int m = ty * 8 + i;
        h0l[i] = hd[(2 * tx)     * XSTR + 2 * m];
        h0h[i] = hd[(2 * tx + 1) * XSTR + 2 * m];
    }
    __syncthreads();   // all reads of hd complete before writes
    #pragma unroll
    for (int i = 0; i < 8; i++) {
        float2 z2 = unpk(az[i]),  r2  = unpk(ar[i]);
        float2 x2 = unpk(axh[i]), rh2 = unpk(arh[i]);
        float zl = sigmoidf_(z2.x), zh = sigmoidf_(z2.y);
        float rl = sigmoidf_(r2.x), rr = sigmoidf_(r2.y);
        float hl = tanhf_(x2.x + rl * rh2.x);
        float hh = tanhf_(x2.y + rr * rh2.y);
        float nl = zl * h0l[i] + (1.f - zl) * hl;
        float nh = zh * h0h[i] + (1.f - zh) * hh;
        int m = ty * 8 + i;
        *reinterpret_cast<float2*>(hd + (2 * tx)     * XSTR + 2 * m) = make_float2(nl, nl);
        *reinterpret_cast<float2*>(hd + (2 * tx + 1) * XSTR + 2 * m) = make_float2(nh, nh);
    }
    __syncthreads();   // writes visible before next step's reads
}

// ---------------- main fused kernel: one CTA owns 32 batch rows ----------------
__global__ void __launch_bounds__(256, 1)
gru_forecast_kernel(const float* __restrict__ inputs,
                    const float* __restrict__ eps_s,
                    float* __restrict__ out)
{
    extern __shared__ float smem[];
    float* xb0 = smem;                        // [NFD][XSTR]
    float* xb1 = xb0 + NFD * XSTR;            // [NFD][XSTR]
    float* hd  = xb1 + NFD * XSTR;            // [128][XSTR]
    float* ys  = hd  + 128 * XSTR;            // [32][OUTS]

    const int tid = threadIdx.x;
    const int tx  = tid & 63;
    const int ty  = tid >> 6;
    const int r0  = blockIdx.x * 32;

    for (int idx = tid; idx < 128 * XSTR; idx += 256) hd[idx] = 0.f;

    // preload x for t=0
    for (int idx = tid; idx < 32 * NFD; idx += 256) {
        int m = idx / NFD, f = idx - m * NFD;
        float v = inputs[(r0 + m) * (TSEQ * NFD) + f];
        *reinterpret_cast<float2*>(xb0 + f * XSTR + 2 * m) = make_float2(v, v);
    }
    __syncthreads();

    // ---- phase 1: 56 warm-up GRU steps, input prefetch overlapped with GEMMs ----
    for (int t = 0; t < LAGT; t++) {
        float* xcur = (t & 1) ? xb1 : xb0;
        float* xnxt = (t & 1) ? xb0 : xb1;
        if (t + 1 < LAGT) {
            for (int idx = tid; idx < 32 * NFD; idx += 256) {
                int m = idx / NFD, f = idx - m * NFD;
                float v = inputs[(r0 + m) * (TSEQ * NFD) + (t + 1) * NFD + f];
                *reinterpret_cast<float2*>(xnxt + f * XSTR + 2 * m) = make_float2(v, v);
            }
        }
        gru_step(xcur, hd, tx, ty);
    }

    // ---- phase 2: 28 variational decode steps ----
    for (int step = 0; step < GAMMA_; step++) {
        if (step > 0) {
            const float* es = eps_s + (step - 1) * (BATCH * NFD);
            for (int idx = tid; idx < 32 * NFD; idx += 256) {
                int m = idx / NFD, f = idx - m * NFD;
                float v = ys[m * OUTS + f] + ys[m * OUTS + NFD + f] * es[(r0 + m) * NFD + f];
                *reinterpret_cast<float2*>(xb0 + f * XSTR + 2 * m) = make_float2(v, v);
            }
            __syncthreads();
            gru_step(xb0, hd, tx, ty);
        }
        // dense: y = h @ wker[step] + wbias[step]  (cols 2tx,2tx+1 and 128+2tx,129+2tx)
        {
            ull ay0[8], ay1[8];
            ull b0v = *reinterpret_cast<const ull*>(g_wbias + step * OUTP + 2 * tx);
            ull b1v = *reinterpret_cast<const ull*>(g_wbias + step * OUTP + 128 + 2 * tx);
            #pragma unroll
            for (int i = 0; i < 8; i++) { ay0[i] = b0v; ay1[i] = b1v; }
            const ull* W = reinterpret_cast<const ull*>(g_wker + step * (UNITS * OUTP)) + tx;
            #pragma unroll 4
            for (int k = 0; k < UNITS; k++) {
                ull wa = W[k * 128], wb = W[k * 128 + 64];
                #pragma unroll
                for (int i = 0; i < 8; i++) {
                    ull xx = *reinterpret_cast<const ull*>(hd + k * XSTR + 2 * (ty * 8 + i));
                    ay0[i] = ffma2(xx, wa, ay0[i]);
                    ay1[i] = ffma2(xx, wb, ay1[i]);
                }
            }
            #pragma unroll
            for (int i = 0; i < 8; i++) {
                float* orow = ys + (ty * 8 + i) * OUTS;
                *reinterpret_cast<ull*>(orow + 2 * tx)       = ay0[i];
                *reinterpret_cast<ull*>(orow + 128 + 2 * tx) = ay1[i];
            }
        }
        __syncthreads();
        // dist params: write output; overwrite ys[:,101:] with scale for next x
        for (int idx = tid; idx < 32 * NFD; idx += 256) {
            int m = idx / NFD, f = idx - m * NFD;
            float loc = ys[m * OUTS + f];
            float sc  = 1e-5f + 0.05f * softplusf_(CCONST + ys[m * OUTS + NFD + f]);
            ys[m * OUTS + NFD + f] = sc;
            int ob = (r0 + m) * (GAMMA_ * OUT2) + step * OUT2;
            out[ob + f]       = loc;
            out[ob + NFD + f] = sc;
        }
        __syncthreads();
    }
}

// ---------------- single merged prep kernel ----------------
__global__ void prep_all(const float* __restrict__ Wk, const float* __restrict__ U,
                         const float* __restrict__ b,
                         const float* __restrict__ dvl, const float* __restrict__ dvr,
                         const float* __restrict__ ew0, const float* __restrict__ ew)
{
    const int gs = gridDim.x * blockDim.x;
    const int t0 = blockIdx.x * blockDim.x + threadIdx.x;

    for (int i = t0; i < NFD * NGP; i += gs) {
        int k = i / NGP, n = i - k * NGP;
        int g = n >> 7, c = n & 127;
        g_Wk[i] = (c < UNITS) ? Wk[k * NG + g * UNITS + c] : 0.f;
    }
    for (int i = t0; i < UNITS * NGP; i += gs) {
        int k = i / NGP, n = i - k * NGP;
        int g = n >> 7, c = n & 127;
        g_U[i] = (c < UNITS) ? U[k * NG + g * UNITS + c] : 0.f;
    }
    for (int n = t0; n < 256; n += gs) {
        int g = n >> 7, c = n & 127;
        g_bzr[n] = (c < UNITS) ? (b[g * UNITS + c] + b[NG + g * UNITS + c]) : 0.f;
    }
    for (int c = t0; c < 128; c += gs) {
        g_bxh[c] = (c < UNITS) ? b[2 * UNITS + c] : 0.f;
        g_brh[c] = (c < UNITS) ? b[NG + 2 * UNITS + c] : 0.f;
    }
    for (int i = t0; i < GAMMA_ * UNITS * OUTP; i += gs) {
        int t = i / (UNITS * OUTP);
        int r = i - t * (UNITS * OUTP);
        int u = r / OUTP;
        int o = r - u * OUTP;
        float w = 0.f;
        if (o < OUT2) {
            int j = u * OUT2 + o;
            float e = (t == 0) ? ew0[j] : ew[(t - 1) * NW + j];
            w = dvl[j] + (1e-5f + 0.01f * softplusf_(CCONST + dvr[j])) * e;
        }
        g_wker[i] = w;
    }
    for (int i = t0; i < GAMMA_ * OUTP; i += gs) {
        int t = i / OUTP, o = i - t * OUTP;
        float w = 0.f;
        if (o < OUT2) {
            int j = KS_ + o;
            float e = (t == 0) ? ew0[j] : ew[(t - 1) * NW + j];
            w = dvl[j] + (1e-5f + 0.01f * softplusf_(CCONST + dvr[j])) * e;
        }
        g_wbias[i] = w;
    }
}

// ---------------- launch ----------------
extern "C" void kernel_launch(void* const* d_in, const int* in_sizes, int n_in,
                              void* d_out, int out_size)
{
    const float* inputs = (const float*)d_in[0];
    const float* Wk     = (const float*)d_in[1];
    const float* U      = (const float*)d_in[2];
    const float* b      = (const float*)d_in[3];
    const float* dvl    = (const float*)d_in[4];
    const float* dvr    = (const float*)d_in[5];
    const float* ew0    = (const float*)d_in[6];
    const float* ew     = (const float*)d_in[7];
    const float* es     = (const float*)d_in[8];
    float* out          = (float*)d_out;
    (void)in_sizes; (void)n_in; (void)out_size;

    const int smem_bytes =
        (2 * NFD * XSTR + 128 * XSTR + 32 * OUTS) * (int)sizeof(float); // 120,144 B
    cudaFuncSetAttribute(gru_forecast_kernel,
                         cudaFuncAttributeMaxDynamicSharedMemorySize, smem_bytes);

    prep_all<<<512, 256>>>(Wk, U, b, dvl, dvr, ew0, ew);
    gru_forecast_kernel<<<BATCH / 32, 256, smem_bytes>>>(inputs, es, out);
}

// round 10
// speedup vs baseline: 1.0676x; 1.0676x over previous
#include <cuda_runtime.h>

// ---------------- problem constants ----------------
#define NFD    101            // feature dim
#define UNITS  125            // GRU units
#define NG     375            // 3*UNITS
#define NGP    384            // gate-padded weight cols: z@0, r@128, h@256
#define OUT2   202            // 2*NFD
#define OUTP   256            // padded dense cols
#define OUTS   258            // ys smem row stride
#define XSTR   66             // xdup/hdup smem row stride (32 dup pairs + pad)
#define KS_    (UNITS*OUT2)   // 25250
#define NW     (KS_+OUT2)     // 25452
#define GAMMA_ 28
#define LAGT   56             // 70 - 14
#define BATCH  4096
#define TSEQ   70
#define NTHR   512
#define CCONST 0.5413248546129181f   // log(expm1(1))

typedef unsigned long long ull;

// ---------------- scratch (device globals: no allocation allowed) ----------------
__device__ __align__(16) float g_Wk[NFD * NGP];            // (101,384) gate-padded
__device__ __align__(16) float g_U [UNITS * NGP];          // (125,384) gate-padded
__device__ __align__(16) float g_bzr[256];                 // z: b0z+b1z @0, r: b0r+b1r @128
__device__ __align__(16) float g_bxh[128];                 // b0 h-gate
__device__ __align__(16) float g_brh[128];                 // b1 h-gate
__device__ __align__(16) float g_wker [GAMMA_ * UNITS * OUTP]; // 28 x (125,256)
__device__ __align__(16) float g_wbias[GAMMA_ * OUTP];

// ---------------- math helpers ----------------
__device__ __forceinline__ float softplusf_(float x) {
    return (x > 20.f) ? x : log1pf(__expf(x));
}
__device__ __forceinline__ float sigmoidf_(float x) {
    return __fdividef(1.f, 1.f + __expf(-x));
}
__device__ __forceinline__ float tanhf_(float x) {
    float e = __expf(2.f * x);
    return 1.f - __fdividef(2.f, e + 1.f);
}
__device__ __forceinline__ ull ffma2(ull a, ull b, ull c) {
    ull d;
    asm("fma.rn.f32x2 %0, %1, %2, %3;" : "=l"(d) : "l"(a), "l"(b), "l"(c));
    return d;
}
__device__ __forceinline__ float2 unpk(ull v) {
    float2 f;
    asm("mov.b64 {%0, %1}, %2;" : "=f"(f.x), "=f"(f.y) : "l"(v));
    return f;
}

// ---------------- one fused GRU step, gates fully register-resident ----------------
// xd: duplicated activations [NFD][XSTR]; hd: duplicated hidden [128][XSTR]
// thread (tx<64, ty<8): rows m = ty*4+i (i<4), unit pair (2tx, 2tx+1) in every gate.
__device__ __forceinline__ void gru_step(const float* __restrict__ xd,
                                         float* __restrict__ hd,
                                         int tx, int ty)
{
    ull az[4], ar[4], axh[4], arh[4];
    {
        ull bz  = *reinterpret_cast<const ull*>(g_bzr + 2 * tx);
        ull br  = *reinterpret_cast<const ull*>(g_bzr + 128 + 2 * tx);
        ull bxh = *reinterpret_cast<const ull*>(g_bxh + 2 * tx);
        ull brh = *reinterpret_cast<const ull*>(g_brh + 2 * tx);
        #pragma unroll
        for (int i = 0; i < 4; i++) { az[i] = bz; ar[i] = br; axh[i] = bxh; arh[i] = brh; }
    }
    const float* xrow = xd + 2 * (ty * 4);
    const float* hrow = hd + 2 * (ty * 4);
    // pass A: x @ Wk  (z,r into shared accs; h-gate into axh)
    {
        const ull* W = reinterpret_cast<const ull*>(g_Wk) + tx;  // row stride 192 ull
        #pragma unroll 4
        for (int k = 0; k < NFD; k++) {
            ull wz = W[k * 192], wr = W[k * 192 + 64], wh = W[k * 192 + 128];
            #pragma unroll
            for (int i = 0; i < 4; i++) {
                ull xx = *reinterpret_cast<const ull*>(xrow + k * XSTR + 2 * i);
                az[i]  = ffma2(xx, wz, az[i]);
                ar[i]  = ffma2(xx, wr, ar[i]);
                axh[i] = ffma2(xx, wh, axh[i]);
            }
        }
    }
    // pass B: h @ U  (z,r continue shared accs; h-gate into arh)
    {
        const ull* W = reinterpret_cast<const ull*>(g_U) + tx;
        #pragma unroll 4
        for (int k = 0; k < UNITS; k++) {
            ull wz = W[k * 192], wr = W[k * 192 + 64], wh = W[k * 192 + 128];
            #pragma unroll
            for (int i = 0; i < 4; i++) {
                ull xx = *reinterpret_cast<const ull*>(hrow + k * XSTR + 2 * i);
                az[i]  = ffma2(xx, wz, az[i]);
                ar[i]  = ffma2(xx, wr, ar[i]);
                arh[i] = ffma2(xx, wh, arh[i]);
            }
        }
    }
    // read old h for the two owned units (before any gate write)
    float h0l[4], h0h[4];
    #pragma unroll
    for (int i = 0; i < 4; i++) {
        int m = ty * 4 + i;
        h0l[i] = hd[(2 * tx)     * XSTR + 2 * m];
        h0h[i] = hd[(2 * tx + 1) * XSTR + 2 * m];
    }
    __syncthreads();   // all reads of hd complete before writes
    #pragma unroll
    for (int i = 0; i < 4; i++) {
        float2 z2 = unpk(az[i]),  r2  = unpk(ar[i]);
        float2 x2 = unpk(axh[i]), rh2 = unpk(arh[i]);
        float zl = sigmoidf_(z2.x), zh = sigmoidf_(z2.y);
        float rl = sigmoidf_(r2.x), rr = sigmoidf_(r2.y);
        float hl = tanhf_(x2.x + rl * rh2.x);
        float hh = tanhf_(x2.y + rr * rh2.y);
        float nl = zl * h0l[i] + (1.f - zl) * hl;
        float nh = zh * h0h[i] + (1.f - zh) * hh;
        int m = ty * 4 + i;
        *reinterpret_cast<float2*>(hd + (2 * tx)     * XSTR + 2 * m) = make_float2(nl, nl);
        *reinterpret_cast<float2*>(hd + (2 * tx + 1) * XSTR + 2 * m) = make_float2(nh, nh);
    }
    __syncthreads();   // writes visible before next step's reads
}

// ---------------- main fused kernel: one CTA owns 32 batch rows ----------------
__global__ void __launch_bounds__(NTHR, 1)
gru_forecast_kernel(const float* __restrict__ inputs,
                    const float* __restrict__ eps_s,
                    float* __restrict__ out)
{
    extern __shared__ float smem[];
    float* xb0 = smem;                        // [NFD][XSTR]
    float* xb1 = xb0 + NFD * XSTR;            // [NFD][XSTR]
    float* hd  = xb1 + NFD * XSTR;            // [128][XSTR]
    float* ys  = hd  + 128 * XSTR;            // [32][OUTS]

    const int tid = threadIdx.x;
    const int tx  = tid & 63;
    const int ty  = tid >> 6;
    const int r0  = blockIdx.x * 32;

    for (int idx = tid; idx < 128 * XSTR; idx += NTHR) hd[idx] = 0.f;

    // preload x for t=0
    for (int idx = tid; idx < 32 * NFD; idx += NTHR) {
        int m = idx / NFD, f = idx - m * NFD;
        float v = inputs[(r0 + m) * (TSEQ * NFD) + f];
        *reinterpret_cast<float2*>(xb0 + f * XSTR + 2 * m) = make_float2(v, v);
    }
    __syncthreads();

    // ---- phase 1: 56 warm-up GRU steps, input prefetch overlapped with GEMMs ----
    for (int t = 0; t < LAGT; t++) {
        float* xcur = (t & 1) ? xb1 : xb0;
        float* xnxt = (t & 1) ? xb0 : xb1;
        if (t + 1 < LAGT) {
            for (int idx = tid; idx < 32 * NFD; idx += NTHR) {
                int m = idx / NFD, f = idx - m * NFD;
                float v = inputs[(r0 + m) * (TSEQ * NFD) + (t + 1) * NFD + f];
                *reinterpret_cast<float2*>(xnxt + f * XSTR + 2 * m) = make_float2(v, v);
            }
        }
        gru_step(xcur, hd, tx, ty);
    }

    // ---- phase 2: 28 variational decode steps ----
    for (int step = 0; step < GAMMA_; step++) {
        if (step > 0) {
            const float* es = eps_s + (step - 1) * (BATCH * NFD);
            for (int idx = tid; idx < 32 * NFD; idx += NTHR) {
                int m = idx / NFD, f = idx - m * NFD;
                float v = ys[m * OUTS + f] + ys[m * OUTS + NFD + f] * es[(r0 + m) * NFD + f];
                *reinterpret_cast<float2*>(xb0 + f * XSTR + 2 * m) = make_float2(v, v);
            }
            __syncthreads();
            gru_step(xb0, hd, tx, ty);
        }
        // dense: y = h @ wker[step] + wbias[step]  (cols 2tx,2tx+1 and 128+2tx,129+2tx)
        {
            ull ay0[4], ay1[4];
            ull b0v = *reinterpret_cast<const ull*>(g_wbias + step * OUTP + 2 * tx);
            ull b1v = *reinterpret_cast<const ull*>(g_wbias + step * OUTP + 128 + 2 * tx);
            #pragma unroll
            for (int i = 0; i < 4; i++) { ay0[i] = b0v; ay1[i] = b1v; }
            const ull* W = reinterpret_cast<const ull*>(g_wker + step * (UNITS * OUTP)) + tx;
            const float* hrow = hd + 2 * (ty * 4);
            #pragma unroll 4
            for (int k = 0; k < UNITS; k++) {
                ull wa = W[k * 128], wb = W[k * 128 + 64];
                #pragma unroll
                for (int i = 0; i < 4; i++) {
                    ull xx = *reinterpret_cast<const ull*>(hrow + k * XSTR + 2 * i);
                    ay0[i] = ffma2(xx, wa, ay0[i]);
                    ay1[i] = ffma2(xx, wb, ay1[i]);
                }
            }
            #pragma unroll
            for (int i = 0; i < 4; i++) {
                float* orow = ys + (ty * 4 + i) * OUTS;
                *reinterpret_cast<ull*>(orow + 2 * tx)       = ay0[i];
                *reinterpret_cast<ull*>(orow + 128 + 2 * tx) = ay1[i];
            }
        }
        __syncthreads();
        // dist params: write output; overwrite ys[:,101:] with scale for next x
        for (int idx = tid; idx < 32 * NFD; idx += NTHR) {
            int m = idx / NFD, f = idx - m * NFD;
            float loc = ys[m * OUTS + f];
            float sc  = 1e-5f + 0.05f * softplusf_(CCONST + ys[m * OUTS + NFD + f]);
            ys[m * OUTS + NFD + f] = sc;
            int ob = (r0 + m) * (GAMMA_ * OUT2) + step * OUT2;
            out[ob + f]       = loc;
            out[ob + NFD + f] = sc;
        }
        __syncthreads();
    }
}

// ---------------- single merged prep kernel ----------------
__global__ void prep_all(const float* __restrict__ Wk, const float* __restrict__ U,
                         const float* __restrict__ b,
                         const float* __restrict__ dvl, const float* __restrict__ dvr,
                         const float* __restrict__ ew0, const float* __restrict__ ew)
{
    const int gs = gridDim.x * blockDim.x;
    const int t0 = blockIdx.x * blockDim.x + threadIdx.x;

    for (int i = t0; i < NFD * NGP; i += gs) {
        int k = i / NGP, n = i - k * NGP;
        int g = n >> 7, c = n & 127;
        g_Wk[i] = (c < UNITS) ? Wk[k * NG + g * UNITS + c] : 0.f;
    }
    for (int i = t0; i < UNITS * NGP; i += gs) {
        int k = i / NGP, n = i - k * NGP;
        int g = n >> 7, c = n & 127;
        g_U[i] = (c < UNITS) ? U[k * NG + g * UNITS + c] : 0.f;
    }
    for (int n = t0; n < 256; n += gs) {
        int g = n >> 7, c = n & 127;
        g_bzr[n] = (c < UNITS) ? (b[g * UNITS + c] + b[NG + g * UNITS + c]) : 0.f;
    }
    for (int c = t0; c < 128; c += gs) {
        g_bxh[c] = (c < UNITS) ? b[2 * UNITS + c] : 0.f;
        g_brh[c] = (c < UNITS) ? b[NG + 2 * UNITS + c] : 0.f;
    }
    for (int i = t0; i < GAMMA_ * UNITS * OUTP; i += gs) {
        int t = i / (UNITS * OUTP);
        int r = i - t * (UNITS * OUTP);
        int u = r / OUTP;
        int o = r - u * OUTP;
        float w = 0.f;
        if (o < OUT2) {
            int j = u * OUT2 + o;
            float e = (t == 0) ? ew0[j] : ew[(t - 1) * NW + j];
            w = dvl[j] + (1e-5f + 0.01f * softplusf_(CCONST + dvr[j])) * e;
        }
        g_wker[i] = w;
    }
    for (int i = t0; i < GAMMA_ * OUTP; i += gs) {
        int t = i / OUTP, o = i - t * OUTP;
        float w = 0.f;
        if (o < OUT2) {
            int j = KS_ + o;
            float e = (t == 0) ? ew0[j] : ew[(t - 1) * NW + j];
            w = dvl[j] + (1e-5f + 0.01f * softplusf_(CCONST + dvr[j])) * e;
        }
        g_wbias[i] = w;
    }
}

// ---------------- launch ----------------
extern "C" void kernel_launch(void* const* d_in, const int* in_sizes, int n_in,
                              void* d_out, int out_size)
{
    const float* inputs = (const float*)d_in[0];
    const float* Wk     = (const float*)d_in[1];
    const float* U      = (const float*)d_in[2];
    const float* b      = (const float*)d_in[3];
    const float* dvl    = (const float*)d_in[4];
    const float* dvr    = (const float*)d_in[5];
    const float* ew0    = (const float*)d_in[6];
    const float* ew     = (const float*)d_in[7];
    const float* es     = (const float*)d_in[8];
    float* out          = (float*)d_out;
    (void)in_sizes; (void)n_in; (void)out_size;

    const int smem_bytes =
        (2 * NFD * XSTR + 128 * XSTR + 32 * OUTS) * (int)sizeof(float); // 120,144 B
    cudaFuncSetAttribute(gru_forecast_kernel,
                         cudaFuncAttributeMaxDynamicSharedMemorySize, smem_bytes);

    prep_all<<<512, 256>>>(Wk, U, b, dvl, dvr, ew0, ew);
    gru_forecast_kernel<<<BATCH / 32, NTHR, smem_bytes>>>(inputs, es, out);
}